// round 2
// baseline (speedup 1.0000x reference)
#include <cuda_runtime.h>
#include <math.h>

// ---------------------------------------------------------------------------
// AdaFaceLoss: mean CE over B=512 rows, C=100000 cols.
// Pass 1 (main_kernel): streaming sum of exp(64*x) per row using a packed
//   f32x2 FMA-pipe fast-exp (no MUFU in the hot loop).
// Pass 2 (finish_kernel, 1 block / 512 threads): norm stats, per-row label
//   margin math, label-column correction, log, batch mean.
// Labels arrive as int32 (JAX x64 disabled downgrades the int64 request).
// ---------------------------------------------------------------------------

#define B_ROWS 512
#define C_COLS 100000
#define NSPLIT 8
#define F4_PER_ROW 25000        // C_COLS / 4
#define F4_PER_BLK 3125         // F4_PER_ROW / NSPLIT
#define THREADS_MAIN 256

// exp(64*x) = 2^(K*x), K = 64*log2(e)
#define KLOG2 92.33248261689366f
#define MAGICF 12582912.0f       // 1.5 * 2^23  (round-to-nearest reduction)
#define PC0 1.0f
#define PC1 0.6931471805599453f
#define PC2 0.2402265069591007f
#define PC3 0.05550410866482158f
#define PC4 0.009618129107628477f

__device__ float g_partials[B_ROWS * NSPLIT];

typedef unsigned long long u64;

// ---- packed f32x2 helpers (sm_100+/sm_103a) ----
__device__ __forceinline__ u64 pk2(float a, float b) {
    u64 r; asm("mov.b64 %0,{%1,%2};" : "=l"(r) : "f"(a), "f"(b)); return r;
}
__device__ __forceinline__ u64 mul2(u64 a, u64 b) {
    u64 r; asm("mul.rn.f32x2 %0,%1,%2;" : "=l"(r) : "l"(a), "l"(b)); return r;
}
__device__ __forceinline__ u64 add2(u64 a, u64 b) {
    u64 r; asm("add.rn.f32x2 %0,%1,%2;" : "=l"(r) : "l"(a), "l"(b)); return r;
}
__device__ __forceinline__ u64 fma2(u64 a, u64 b, u64 c) {
    u64 r; asm("fma.rn.f32x2 %0,%1,%2,%3;" : "=l"(r) : "l"(a), "l"(b), "l"(c)); return r;
}

// Scalar replica of the packed fast-exp: MUST match the packed op sequence
// bitwise (.rn ops, same constants, same order) so the label-column term
// cancels exactly in the epilogue.
__device__ __forceinline__ float fast_exp_scalar(float x) {
    float t = __fmul_rn(x, KLOG2);
    float z = __fadd_rn(t, MAGICF);
    float zn = __fmaf_rn(z, -1.0f, MAGICF);      // -round(t)
    float f = __fmaf_rn(x, KLOG2, zn);           // exact t - round(t)
    float p = __fmaf_rn(PC4, f, PC3);
    p = __fmaf_rn(p, f, PC2);
    p = __fmaf_rn(p, f, PC1);
    p = __fmaf_rn(p, f, PC0);
    unsigned zi = __float_as_uint(z);
    unsigned r = __float_as_uint(p) + (zi << 23);
    return __uint_as_float(r);
}

// Process one packed pair: accumulates the two exp values.
__device__ __forceinline__ void exp_pack_acc(u64 x, u64 K2, u64 M2, u64 N1,
                                             u64 C42, u64 C32, u64 C22, u64 C12, u64 C02,
                                             float& a0, float& a1) {
    u64 t = mul2(x, K2);
    u64 z = add2(t, M2);
    u64 zn = fma2(z, N1, M2);        // M - z = -round(t)
    u64 f = fma2(x, K2, zn);
    u64 p = fma2(C42, f, C32);
    p = fma2(p, f, C22);
    p = fma2(p, f, C12);
    p = fma2(p, f, C02);
    unsigned zl = (unsigned)z, zh = (unsigned)(z >> 32);
    unsigned pl = (unsigned)p, ph = (unsigned)(p >> 32);
    a0 += __uint_as_float(pl + (zl << 23));
    a1 += __uint_as_float(ph + (zh << 23));
}

__global__ __launch_bounds__(THREADS_MAIN)
void main_kernel(const float* __restrict__ logits) {
    const int b = blockIdx.x;
    const int row = b >> 3;
    const int split = b & 7;

    const ulonglong2* __restrict__ base =
        (const ulonglong2*)(logits + (size_t)row * C_COLS) + (size_t)split * F4_PER_BLK;

    const u64 K2 = pk2(KLOG2, KLOG2);
    const u64 M2 = pk2(MAGICF, MAGICF);
    const u64 N1 = pk2(-1.0f, -1.0f);
    const u64 C42 = pk2(PC4, PC4);
    const u64 C32 = pk2(PC3, PC3);
    const u64 C22 = pk2(PC2, PC2);
    const u64 C12 = pk2(PC1, PC1);
    const u64 C02 = pk2(PC0, PC0);

    float s0 = 0.f, s1 = 0.f, s2 = 0.f, s3 = 0.f;

    int i = threadIdx.x;
    // Batched main loop: 4 LDG.128 in flight per thread (MLP).
    for (; i + 768 < F4_PER_BLK; i += 4 * THREADS_MAIN) {
        ulonglong2 v0 = base[i];
        ulonglong2 v1 = base[i + THREADS_MAIN];
        ulonglong2 v2 = base[i + 2 * THREADS_MAIN];
        ulonglong2 v3 = base[i + 3 * THREADS_MAIN];
        exp_pack_acc(v0.x, K2, M2, N1, C42, C32, C22, C12, C02, s0, s1);
        exp_pack_acc(v0.y, K2, M2, N1, C42, C32, C22, C12, C02, s2, s3);
        exp_pack_acc(v1.x, K2, M2, N1, C42, C32, C22, C12, C02, s0, s1);
        exp_pack_acc(v1.y, K2, M2, N1, C42, C32, C22, C12, C02, s2, s3);
        exp_pack_acc(v2.x, K2, M2, N1, C42, C32, C22, C12, C02, s0, s1);
        exp_pack_acc(v2.y, K2, M2, N1, C42, C32, C22, C12, C02, s2, s3);
        exp_pack_acc(v3.x, K2, M2, N1, C42, C32, C22, C12, C02, s0, s1);
        exp_pack_acc(v3.y, K2, M2, N1, C42, C32, C22, C12, C02, s2, s3);
    }
    // Tail
    for (; i < F4_PER_BLK; i += THREADS_MAIN) {
        ulonglong2 v = base[i];
        exp_pack_acc(v.x, K2, M2, N1, C42, C32, C22, C12, C02, s0, s1);
        exp_pack_acc(v.y, K2, M2, N1, C42, C32, C22, C12, C02, s2, s3);
    }

    float s = (s0 + s1) + (s2 + s3);
    // warp reduce
    #pragma unroll
    for (int o = 16; o > 0; o >>= 1)
        s += __shfl_down_sync(0xffffffffu, s, o);

    __shared__ float ws[THREADS_MAIN / 32];
    const int warp = threadIdx.x >> 5;
    const int lane = threadIdx.x & 31;
    if (lane == 0) ws[warp] = s;
    __syncthreads();
    if (threadIdx.x == 0) {
        float tot = 0.f;
        #pragma unroll
        for (int w = 0; w < THREADS_MAIN / 32; w++) tot += ws[w];
        g_partials[row * NSPLIT + split] = tot;
    }
}

// block-wide sum over 512 threads
__device__ __forceinline__ float block_sum_512(float v, float* red) {
    #pragma unroll
    for (int o = 16; o > 0; o >>= 1)
        v += __shfl_down_sync(0xffffffffu, v, o);
    const int w = threadIdx.x >> 5;
    const int l = threadIdx.x & 31;
    if (l == 0) red[w] = v;
    __syncthreads();
    float t = 0.f;
    if (w == 0) {
        t = (l < 16) ? red[l] : 0.f;
        #pragma unroll
        for (int o = 8; o > 0; o >>= 1)
            t += __shfl_down_sync(0xffffffffu, t, o);
        if (l == 0) red[0] = t;
    }
    __syncthreads();
    float r = red[0];
    __syncthreads();
    return r;
}

__global__ __launch_bounds__(512)
void finish_kernel(const float* __restrict__ logits,
                   const float* __restrict__ norms,
                   const int* __restrict__ labels,
                   float* __restrict__ out) {
    __shared__ float red[16];
    const int tid = threadIdx.x;

    // --- norm statistics (mean, std ddof=1) ---
    float sn = fminf(fmaxf(norms[tid], 0.001f), 100.0f);
    float mean = block_sum_512(sn, red) * (1.0f / 512.0f);
    float d = sn - mean;
    float var = block_sum_512(d * d, red) * (1.0f / 511.0f);
    float stdv = sqrtf(var);

    float ms = (sn - mean) / (stdv + 1e-6f) * 0.333f;
    ms = fminf(fmaxf(ms, -1.0f), 1.0f);

    // --- label-column margin math ---
    int lab = labels[tid];
    lab = max(0, min(lab, C_COLS - 1));   // defensive clamp: no OOB ever
    const float x = logits[(size_t)tid * C_COLS + lab];
    float cosine = fminf(fmaxf(x, -1.0f + 1e-6f), 1.0f - 1e-6f);
    float theta = acosf(cosine);
    float g_ang = -0.4f * ms;
    float theta_m = fminf(fmaxf(theta + g_ang, 1e-6f),
                          3.14159265358979323846f - 1e-6f);
    float g_add = 0.4f + 0.4f * ms;
    float cos_m = cosf(theta_m) - g_add;
    float smod = cos_m * 64.0f;

    // --- corrected row sum: swap plain label term for modified one ---
    float sum = 0.f;
    #pragma unroll
    for (int s = 0; s < NSPLIT; s++) sum += g_partials[tid * NSPLIT + s];
    sum += expf(smod) - fast_exp_scalar(x);

    float nll = logf(sum) - smod;

    float total = block_sum_512(nll, red);
    if (tid == 0) out[0] = total * (1.0f / 512.0f);
}

extern "C" void kernel_launch(void* const* d_in, const int* in_sizes, int n_in,
                              void* d_out, int out_size) {
    const float* logits = (const float*)d_in[0];
    const float* norms = (const float*)d_in[1];
    const int* labels = (const int*)d_in[2];
    float* out = (float*)d_out;

    main_kernel<<<B_ROWS * NSPLIT, THREADS_MAIN>>>(logits);
    finish_kernel<<<1, 512>>>(logits, norms, labels, out);
}